// round 16
// baseline (speedup 1.0000x reference)
#include <cuda_runtime.h>
#include <cuda_bf16.h>
#include <cstdint>

#define NGRAPH 4096
#define EPS 1e-6f

// ---------------- device scratch ----------------
__device__ __align__(16) float g_att[262144 * 8];          // exp attention, unnormalized [N,8]
__device__ __align__(16) float g_outflat[NGRAPH * 1024];   // aggregated [B, H*D]
__device__ __align__(16) unsigned int g_W1h[64 * 64];      // W1 packed bf16x2 [n][kw]
__device__ __align__(16) unsigned int g_W1l[64 * 64];
__device__ __align__(16) unsigned int g_W3h[128 * 512];    // W3 packed [n][kw]
__device__ __align__(16) unsigned int g_W3l[128 * 512];
__device__ __align__(16) unsigned int g_W4h[128 * 64];     // W4 packed [n][kw]
__device__ __align__(16) unsigned int g_W4l[128 * 64];
__device__ int g_seglo[NGRAPH + 1];
__device__ int g_is64;

__device__ __forceinline__ float leaky(float x){ return x > 0.f ? x : 0.01f * x; }

// split (x,y) into bf16 hi/lo pairs packed as bf16x2 words (x in LOW half).
__device__ __forceinline__ void split2(float x, float y, uint32_t& h, uint32_t& l){
    __nv_bfloat16 hx = __float2bfloat16_rn(x);
    __nv_bfloat16 hy = __float2bfloat16_rn(y);
    float rx = x - __bfloat162float(hx);
    float ry = y - __bfloat162float(hy);
    __nv_bfloat162 hh = __halves2bfloat162(hx, hy);           // .x = low half
    __nv_bfloat162 ll = __halves2bfloat162(__float2bfloat16_rn(rx), __float2bfloat16_rn(ry));
    h = *reinterpret_cast<uint32_t*>(&hh);
    l = *reinterpret_cast<uint32_t*>(&ll);
}

// D += A(16x16 bf16) * B(16x8 bf16), fp32 accumulate
__device__ __forceinline__ void mma_bf16(float* c,
    uint32_t a0, uint32_t a1, uint32_t a2, uint32_t a3, uint32_t b0, uint32_t b1){
    asm volatile(
      "mma.sync.aligned.m16n8k16.row.col.f32.bf16.bf16.f32 "
      "{%0,%1,%2,%3}, {%4,%5,%6,%7}, {%8,%9}, {%0,%1,%2,%3};\n"
      : "+f"(c[0]), "+f"(c[1]), "+f"(c[2]), "+f"(c[3])
      : "r"(a0), "r"(a1), "r"(a2), "r"(a3), "r"(b0), "r"(b1));
}

// ldmatrix x4 (non-transposed, b16)
__device__ __forceinline__ void ldsm_x4(uint32_t& r0, uint32_t& r1, uint32_t& r2, uint32_t& r3,
                                        uint32_t addr){
    asm volatile("ldmatrix.sync.aligned.m8n8.x4.shared.b16 {%0,%1,%2,%3}, [%4];"
        : "=r"(r0), "=r"(r1), "=r"(r2), "=r"(r3) : "r"(addr));
}

// Parallel batch dtype detection (int32 loads only).
__global__ void detect_kernel(const int* __restrict__ batch, int n){
    __shared__ int bad;
    if (threadIdx.x == 0) bad = 0;
    __syncthreads();
    int base = n / 2;
    int i = threadIdx.x;
    int lo = batch[base + 2*i];
    int hi = batch[base + 2*i + 1];
    if (hi != 0 || lo < 0 || lo >= NGRAPH) bad = 1;
    __syncthreads();
    if (threadIdx.x == 0) g_is64 = (bad == 0);
}

__device__ __forceinline__ int bat(const int* b, int i, int is64){
    return is64 ? b[2*i] : b[i];
}

__device__ __forceinline__ int lbound(const int* b, int n, int val, int is64){
    int lo = 0, hi = n;
    while (lo < hi){
        int mid = (lo + hi) >> 1;
        if (bat(b, mid, is64) < val) lo = mid + 1; else hi = mid;
    }
    return lo;
}

// ---------------- segment bounds: one thread per graph ----------------
__global__ void bounds_kernel(const int* __restrict__ batch, int n){
    int g = blockIdx.x * 256 + threadIdx.x;
    int is64 = g_is64;
    if (g < NGRAPH) g_seglo[g] = lbound(batch, n, g, is64);
    if (g == 0)     g_seglo[NGRAPH] = n;
}

// ---------------- weight prep: pack W1/W3/W4 as bf16x2 hi/lo, [n][kword] ----------------
__global__ void prep_kernel(const float* __restrict__ W1,
                            const float* __restrict__ W3,
                            const float* __restrict__ W4){
    int idx = blockIdx.x * 256 + threadIdx.x;
    if (idx < 4096){                               // W1: [128 k][64 n] -> [64 n][64 kw]
        int n = idx >> 6, kw = idx & 63;
        uint32_t h, l;
        split2(W1[(2*kw)*64 + n], W1[(2*kw+1)*64 + n], h, l);
        g_W1h[idx] = h; g_W1l[idx] = l;
        return;
    }
    int j = idx - 4096;
    if (j < 65536){                                // W3: [1024 k][128 n] -> [128 n][512 kw]
        int n = j >> 9, kw = j & 511;
        uint32_t h, l;
        split2(W3[(2*kw)*128 + n], W3[(2*kw+1)*128 + n], h, l);
        g_W3h[j] = h; g_W3l[j] = l;
        return;
    }
    int m = j - 65536;
    if (m < 8192){                                 // W4: [128 k][128 n] -> [128 n][64 kw]
        int n = m >> 6, kw = m & 63;
        uint32_t h, l;
        split2(W4[(2*kw)*128 + n], W4[(2*kw+1)*128 + n], h, l);
        g_W4h[m] = h; g_W4l[m] = l;
    }
}

// ---------------- Pass A: GEMM1 (bf16 3-term, ldmatrix) + leaky + LN + GEMM2 + exp ----------------
// 64 rows / block, 256 threads, 4096 blocks, smem 71.9 KB -> 3 CTAs/SM (occ 37.5%).
// Warp (mw in 0..3, nw in 0..1): rows [mw*16, +16), cols [nw*32, +32).
#define ATT_SMEM_WORDS (4352 + 4352 + 4352 + 4352 + 512 + 64*3 + 8 + 128)

__global__ __launch_bounds__(256) void att_kernel(
    const float* __restrict__ feat,
    const float* __restrict__ b1,
    const float* __restrict__ g1, const float* __restrict__ be1,
    const float* __restrict__ W2, const float* __restrict__ b2)
{
    extern __shared__ uint32_t smw[];
    uint32_t* sAh = smw;                 // 64 x 68 = 4352
    uint32_t* sAl = sAh + 4352;          // 4352
    uint32_t* sWh = sAl + 4352;          // 64 x 68 = 4352
    uint32_t* sWl = sWh + 4352;          // 4352
    float* sW2  = (float*)(sWl + 4352);  // 512
    float* sB1  = sW2 + 512;             // 64
    float* sG1  = sB1 + 64;              // 64
    float* sBe1 = sG1 + 64;              // 64
    float* sB2  = sBe1 + 64;             // 8
    float* sMu  = sB2 + 8;               // 64
    float* sIs  = sMu + 64;              // 64
    float* sH   = (float*)sAh;           // alias, stride 65 (4160 <= 4352)

    int t = threadIdx.x;
    int row0 = blockIdx.x * 64;
    int wid = t >> 5, lane = t & 31;
    int g = lane >> 2, t4 = lane & 3;
    int mw = wid & 3, nw = wid >> 2;

    {   // stage A: feat 64x128 -> bf16 hi/lo packed (2048 float4, 8/thread), STS.64
        const float4* gsrc = (const float4*)(feat + (size_t)row0 * 128);
        #pragma unroll
        for (int e = 0; e < 8; e++){
            int i4 = t + 256*e;
            int r = i4 >> 5, c4 = i4 & 31;
            float4 a = gsrc[i4];
            uint2 h, l;
            split2(a.x, a.y, h.x, l.x);
            split2(a.z, a.w, h.y, l.y);
            int base = r*68 + 2*c4;
            *(uint2*)&sAh[base] = h;
            *(uint2*)&sAl[base] = l;
        }
    }
    {   // stage B: copy prepacked W1 hi/lo (1024 uint4 each, 4/thread)
        #pragma unroll
        for (int e = 0; e < 4; e++){
            int i4 = t + 256*e;
            int n = i4 >> 4, c4 = i4 & 15;
            *(uint4*)&sWh[n*68 + 4*c4] = *(const uint4*)&g_W1h[n*64 + 4*c4];
            *(uint4*)&sWl[n*68 + 4*c4] = *(const uint4*)&g_W1l[n*64 + 4*c4];
        }
    }
    if (t < 128) ((float4*)sW2)[t] = ((const float4*)W2)[t];
    if (t < 64){ sB1[t] = b1[t]; sG1[t] = g1[t]; sBe1[t] = be1[t]; }
    if (t < 8)  sB2[t] = b2[t];
    __syncthreads();

    // GEMM1: warp = rows [mw*16,+16) x cols [nw*32,+32). K=128 -> 8 k16-steps.
    float acc[4][4];
    #pragma unroll
    for (int jn = 0; jn < 4; jn++){
        acc[jn][0]=0.f; acc[jn][1]=0.f; acc[jn][2]=0.f; acc[jn][3]=0.f;
    }

    uint32_t aBaseH, aBaseL;
    {
        int rowf = mw*16 + (lane & 7) + ((lane >> 3) & 1) * 8;
        int kws  = ((lane >> 4) & 1) * 4;
        aBaseH = (uint32_t)__cvta_generic_to_shared(sAh + rowf*68 + kws);
        aBaseL = (uint32_t)__cvta_generic_to_shared(sAl + rowf*68 + kws);
    }
    uint32_t bBaseH[2], bBaseL[2];
    #pragma unroll
    for (int jp = 0; jp < 2; jp++){
        int nf  = nw*32 + (2*jp + ((lane >> 4) & 1)) * 8 + (lane & 7);
        int kws = ((lane >> 3) & 1) * 4;
        bBaseH[jp] = (uint32_t)__cvta_generic_to_shared(sWh + nf*68 + kws);
        bBaseL[jp] = (uint32_t)__cvta_generic_to_shared(sWl + nf*68 + kws);
    }

    #pragma unroll 2
    for (int ks = 0; ks < 8; ks++){
        uint32_t off = (uint32_t)ks * 32;   // 8 words per k16-step
        uint32_t ah0,ah1,ah2,ah3, al0,al1,al2,al3;
        ldsm_x4(ah0,ah1,ah2,ah3, aBaseH + off);
        ldsm_x4(al0,al1,al2,al3, aBaseL + off);
        #pragma unroll
        for (int jp = 0; jp < 2; jp++){
            uint32_t bh0,bh1,bh2,bh3, bl0,bl1,bl2,bl3;
            ldsm_x4(bh0,bh1,bh2,bh3, bBaseH[jp] + off);
            ldsm_x4(bl0,bl1,bl2,bl3, bBaseL[jp] + off);
            mma_bf16(acc[2*jp],   ah0,ah1,ah2,ah3, bh0,bh1);
            mma_bf16(acc[2*jp],   al0,al1,al2,al3, bh0,bh1);
            mma_bf16(acc[2*jp],   ah0,ah1,ah2,ah3, bl0,bl1);
            mma_bf16(acc[2*jp+1], ah0,ah1,ah2,ah3, bh2,bh3);
            mma_bf16(acc[2*jp+1], al0,al1,al2,al3, bh2,bh3);
            mma_bf16(acc[2*jp+1], ah0,ah1,ah2,ah3, bl2,bl3);
        }
    }
    __syncthreads();   // all sAh/sAl reads done before aliasing sAh as sH

    {   // epilogue: bias + leaky -> sH (stride 65)
        int rA = mw*16 + g, rB = rA + 8;
        #pragma unroll
        for (int jn = 0; jn < 4; jn++){
            int c = nw*32 + jn*8 + 2*t4;
            sH[rA*65 + c]     = leaky(acc[jn][0] + sB1[c]);
            sH[rA*65 + c + 1] = leaky(acc[jn][1] + sB1[c+1]);
            sH[rB*65 + c]     = leaky(acc[jn][2] + sB1[c]);
            sH[rB*65 + c + 1] = leaky(acc[jn][3] + sB1[c+1]);
        }
    }
    __syncthreads();

    if (t < 64){   // LN stats per row
        float sum = 0.f, ss = 0.f;
        #pragma unroll 8
        for (int j = 0; j < 64; j++){ float v = sH[t*65 + j]; sum += v; ss += v*v; }
        float mu = sum * (1.f/64.f);
        float var = ss * (1.f/64.f) - mu*mu;
        sMu[t] = mu; sIs[t] = rsqrtf(var + EPS);
    }
    __syncthreads();

    if (t < 128){   // GEMM2 (64->8) + exp (fp32, exact), 2 threads per row
        int row = t >> 1, half = t & 1, kb = half * 4;
        float mu = sMu[row], is = sIs[row];
        float a0=0.f, a1=0.f, a2=0.f, a3=0.f;
        #pragma unroll 4
        for (int j = 0; j < 64; j++){
            float hn = (sH[row*65 + j] - mu) * is * sG1[j] + sBe1[j];
            a0 += hn * sW2[j*8 + kb + 0];
            a1 += hn * sW2[j*8 + kb + 1];
            a2 += hn * sW2[j*8 + kb + 2];
            a3 += hn * sW2[j*8 + kb + 3];
        }
        int grow = row0 + row;
        float4 o;
        o.x = __expf(a0 + sB2[kb+0]);
        o.y = __expf(a1 + sB2[kb+1]);
        o.z = __expf(a2 + sB2[kb+2]);
        o.w = __expf(a3 + sB2[kb+3]);
        *(float4*)&g_att[grow*8 + kb] = o;
    }
}

// ---------------- Pass B: segment softmax + aggregation, 2 heads/thread ----------------
__global__ __launch_bounds__(256) void aggregate_kernel(const float* __restrict__ feat){
    int gi = blockIdx.x;
    __shared__ __align__(16) float sF[32][128];
    __shared__ __align__(16) float sAtt[32][8];
    __shared__ __align__(16) float sRed[128][8];    // rg=1 partial acc
    __shared__ float sS[128][2];                    // rg=1 partial head sums

    int t = threadIdx.x;
    int lo = g_seglo[gi], hi = g_seglo[gi + 1];
    int rg = t >> 7;              // 0 or 1
    int slot = t & 127;
    int hp = slot >> 5;           // head pair 0..3 -> heads 2hp, 2hp+1
    int cq = slot & 31;           // col quad

    float4 acc0 = make_float4(0.f,0.f,0.f,0.f);
    float4 acc1 = make_float4(0.f,0.f,0.f,0.f);
    float ss0 = 0.f, ss1 = 0.f;

    for (int base = lo; base < hi; base += 32){
        int cnt = min(32, hi - base);
        __syncthreads();
        for (int idx4 = t; idx4 < cnt*32; idx4 += 256){
            int r = idx4 >> 5, c4 = idx4 & 31;
            *(float4*)&sF[r][4*c4] = *(const float4*)&feat[(size_t)(base + r) * 128 + 4*c4];
        }
        if (t < cnt*8){
            int r = t >> 3, k = t & 7;
            sAtt[r][k] = g_att[(base + r)*8 + k];
        }
        __syncthreads();
        int rlo = rg * 16, rhi = min(cnt, rlo + 16);
        for (int r = rlo; r < rhi; r++){
            float a0 = sAtt[r][2*hp];
            float a1 = sAtt[r][2*hp + 1];
            ss0 += a0; ss1 += a1;
            float4 f = *(const float4*)&sF[r][cq*4];
            acc0.x += a0*f.x; acc0.y += a0*f.y; acc0.z += a0*f.z; acc0.w += a0*f.w;
            acc1.x += a1*f.x; acc1.y += a1*f.y; acc1.z += a1*f.z; acc1.w += a1*f.w;
        }
    }
    __syncthreads();
    if (rg == 1){
        *(float4*)&sRed[slot][0] = acc0;
        *(float4*)&sRed[slot][4] = acc1;
        sS[slot][0] = ss0; sS[slot][1] = ss1;
    }
    __syncthreads();
    if (rg == 0){
        float4 p0 = *(const float4*)&sRed[slot][0];
        float4 p1 = *(const float4*)&sRed[slot][4];
        acc0.x += p0.x; acc0.y += p0.y; acc0.z += p0.z; acc0.w += p0.w;
        acc1.x += p1.x; acc1.y += p1.y; acc1.z += p1.z; acc1.w += p1.w;
        float tot0 = ss0 + sS[slot][0];
        float tot1 = ss1 + sS[slot][1];
        float inv0 = (hi > lo) ? 1.f / tot0 : 0.f;
        float inv1 = (hi > lo) ? 1.f / tot1 : 0.f;
        acc0.x *= inv0; acc0.y *= inv0; acc0.z *= inv0; acc0.w *= inv0;
        acc1.x *= inv1; acc1.y *= inv1; acc1.z *= inv1; acc1.w *= inv1;
        *(float4*)&g_outflat[(size_t)gi*1024 + (2*hp)*128 + cq*4]     = acc0;
        *(float4*)&g_outflat[(size_t)gi*1024 + (2*hp + 1)*128 + cq*4] = acc1;
    }
}

// ---------------- Pass C: GEMM3(bf16 3-term)+leaky+LN, GEMM4(bf16 3-term)+leaky+LN ----------------
// 16 graphs / block, 256 blocks, 256 threads. Warp w owns n-cols [w*16, +16).
#define FIN_SMEM_WORDS (8704 + 8704 + 1088 + 1088 + 2112 + 128*6 + 32)

__global__ __launch_bounds__(256) void final_kernel(
    const float* __restrict__ b3,
    const float* __restrict__ g3, const float* __restrict__ be3,
    const float* __restrict__ b4,
    const float* __restrict__ g4, const float* __restrict__ be4,
    float* __restrict__ out)
{
    extern __shared__ uint32_t smw[];
    uint32_t* sWh = smw;                 // 128 x 68 = 8704
    uint32_t* sWl = sWh + 8704;          // 8704
    uint32_t* sAh = sWl + 8704;          // 16 x 68 = 1088
    uint32_t* sAl = sAh + 1088;          // 1088
    float* sO1 = (float*)(sAl + 1088);   // 16 x 132 = 2112 (fp32 scratch)
    float* sB3 = sO1 + 2112;
    float* sG3 = sB3 + 128;
    float* sBe3= sG3 + 128;
    float* sB4 = sBe3+ 128;
    float* sG4 = sB4 + 128;
    float* sBe4= sG4 + 128;
    float* sMu = sBe4+ 128;              // 16
    float* sIs = sMu + 16;               // 16

    int t = threadIdx.x;
    int g0 = blockIdx.x * 16;
    int wid = t >> 5, lane = t & 31;
    int g = lane >> 2, t4 = lane & 3;

    if (t < 128){
        sB3[t]=b3[t]; sG3[t]=g3[t]; sBe3[t]=be3[t];
        sB4[t]=b4[t]; sG4[t]=g4[t]; sBe4[t]=be4[t];
    }

    uint32_t aBaseH, aBaseL, bBaseH, bBaseL;
    {
        int rowf = (lane & 7) + ((lane >> 3) & 1) * 8;
        int kwsA = ((lane >> 4) & 1) * 4;
        aBaseH = (uint32_t)__cvta_generic_to_shared(sAh + rowf*68 + kwsA);
        aBaseL = (uint32_t)__cvta_generic_to_shared(sAl + rowf*68 + kwsA);
        int nf   = wid*16 + ((lane >> 4) & 1) * 8 + (lane & 7);
        int kwsB = ((lane >> 3) & 1) * 4;
        bBaseH = (uint32_t)__cvta_generic_to_shared(sWh + nf*68 + kwsB);
        bBaseL = (uint32_t)__cvta_generic_to_shared(sWl + nf*68 + kwsB);
    }

    // ---- GEMM3: [16,1024] @ [1024,128], 8 k-tiles of 128 (8 k16-steps each) ----
    float acc[2][4];
    acc[0][0]=acc[0][1]=acc[0][2]=acc[0][3]=0.f;
    acc[1][0]=acc[1][1]=acc[1][2]=acc[1][3]=0.f;

    for (int kt = 0; kt < 8; kt++){
        __syncthreads();
        {   // stage A slice 16x128 -> bf16 hi/lo (512 float4, 2/thread)
            #pragma unroll
            for (int e = 0; e < 2; e++){
                int i4 = t + 256*e;
                int r = i4 >> 5, c4 = i4 & 31;
                float4 a = *(const float4*)&g_outflat[(size_t)(g0 + r)*1024 + kt*128 + 4*c4];
                uint2 h, l;
                split2(a.x, a.y, h.x, l.x);
                split2(a.z, a.w, h.y, l.y);
                int base = r*68 + 2*c4;
                *(uint2*)&sAh[base] = h;
                *(uint2*)&sAl[base] = l;
            }
        }
        {   // stage W3 hi/lo k-tile
            #pragma unroll
            for (int e = 0; e < 8; e++){
                int i4 = t + 256*e;
                int n = i4 >> 4, c4 = i4 & 15;
                *(uint4*)&sWh[n*68 + 4*c4] = *(const uint4*)&g_W3h[n*512 + kt*64 + 4*c4];
                *(uint4*)&sWl[n*68 + 4*c4] = *(const uint4*)&g_W3l[n*512 + kt*64 + 4*c4];
            }
        }
        __syncthreads();

        #pragma unroll 2
        for (int ks = 0; ks < 8; ks++){
            uint32_t off = (uint32_t)ks * 32;
            uint32_t ah0,ah1,ah2,ah3, al0,al1,al2,al3;
            ldsm_x4(ah0,ah1,ah2,ah3, aBaseH + off);
            ldsm_x4(al0,al1,al2,al3, aBaseL + off);
            uint32_t bh0,bh1,bh2,bh3, bl0,bl1,bl2,bl3;
            ldsm_x4(bh0,bh1,bh2,bh3, bBaseH + off);
            ldsm_x4(bl0,bl1,bl2,bl3, bBaseL + off);
            mma_bf16(acc[0], ah0,ah1,ah2,ah3, bh0,bh1);
            mma_bf16(acc[0], al0,al1,al2,al3, bh0,bh1);
            mma_bf16(acc[0], ah0,ah1,ah2,ah3, bl0,bl1);
            mma_bf16(acc[1], ah0,ah1,ah2,ah3, bh2,bh3);
            mma_bf16(acc[1], al0,al1,al2,al3, bh2,bh3);
            mma_bf16(acc[1], ah0,ah1,ah2,ah3, bl2,bl3);
        }
    }
    __syncthreads();

    {   // epilogue GEMM3 -> sO1 (fp32); stage W4 hi/lo into sWh/sWl
        #pragma unroll
        for (int jj = 0; jj < 2; jj++){
            int c = wid*16 + jj*8 + 2*t4;
            sO1[g*132 + c]       = leaky(acc[jj][0] + sB3[c]);
            sO1[g*132 + c + 1]   = leaky(acc[jj][1] + sB3[c+1]);
            sO1[(g+8)*132 + c]   = leaky(acc[jj][2] + sB3[c]);
            sO1[(g+8)*132 + c+1] = leaky(acc[jj][3] + sB3[c+1]);
        }
        #pragma unroll
        for (int e = 0; e < 8; e++){
            int i4 = t + 256*e;
            int n = i4 >> 4, c4 = i4 & 15;
            *(uint4*)&sWh[n*68 + 4*c4] = *(const uint4*)&g_W4h[n*64 + 4*c4];
            *(uint4*)&sWl[n*68 + 4*c4] = *(const uint4*)&g_W4l[n*64 + 4*c4];
        }
    }
    __syncthreads();

    if (t < 16){   // LN1 stats
        float sum = 0.f, ss = 0.f;
        #pragma unroll 8
        for (int j = 0; j < 128; j++){ float v = sO1[t*132 + j]; sum += v; ss += v*v; }
        float mu = sum * (1.f/128.f);
        float var = ss * (1.f/128.f) - mu*mu;
        sMu[t] = mu; sIs[t] = rsqrtf(var + EPS);
    }
    __syncthreads();
    {   // LN1 apply + bf16 split into sAh/sAl (1024 words, 4/thread)
        #pragma unroll
        for (int e = 0; e < 4; e++){
            int w = t + 256*e;
            int r = w >> 6, kw = w & 63;
            int c = 2*kw;
            float mu = sMu[r], is = sIs[r];
            float v0 = (sO1[r*132 + c]     - mu) * is * sG3[c]   + sBe3[c];
            float v1 = (sO1[r*132 + c + 1] - mu) * is * sG3[c+1] + sBe3[c+1];
            uint32_t h, l;
            split2(v0, v1, h, l);
            sAh[r*68 + kw] = h;
            sAl[r*68 + kw] = l;
        }
    }
    __syncthreads();

    // ---- GEMM4: [16,128] @ [128,128] (8 k16-steps) ----
    float acc2[2][4];
    acc2[0][0]=acc2[0][1]=acc2[0][2]=acc2[0][3]=0.f;
    acc2[1][0]=acc2[1][1]=acc2[1][2]=acc2[1][3]=0.f;

    #pragma unroll 2
    for (int ks = 0; ks < 8; ks++){
        uint32_t off = (uint32_t)ks * 32;
        uint32_t ah0,ah1,ah2,ah3, al0,al1,al2,al3;
        ldsm_x4(ah0,ah1,ah2,ah3, aBaseH + off);
        ldsm_x4(al0,al1,al2,al3, aBaseL + off);
        uint32_t bh0,bh1,bh2,bh3, bl0,bl1,bl2,bl3;
        ldsm_x4(bh0,bh1,bh2,bh3, bBaseH + off);
        ldsm_x4(bl0,bl1,bl2,bl3, bBaseL + off);
        mma_bf16(acc2[0], ah0,ah1,ah2,ah3, bh0,bh1);
        mma_bf16(acc2[0], al0,al1,al2,al3, bh0,bh1);
        mma_bf16(acc2[0], ah0,ah1,ah2,ah3, bl0,bl1);
        mma_bf16(acc2[1], ah0,ah1,ah2,ah3, bh2,bh3);
        mma_bf16(acc2[1], al0,al1,al2,al3, bh2,bh3);
        mma_bf16(acc2[1], ah0,ah1,ah2,ah3, bl2,bl3);
    }
    __syncthreads();

    // epilogue GEMM4 -> sO1 (reuse as sO2)
    #pragma unroll
    for (int jj = 0; jj < 2; jj++){
        int c = wid*16 + jj*8 + 2*t4;
        sO1[g*132 + c]       = leaky(acc2[jj][0] + sB4[c]);
        sO1[g*132 + c + 1]   = leaky(acc2[jj][1] + sB4[c+1]);
        sO1[(g+8)*132 + c]   = leaky(acc2[jj][2] + sB4[c]);
        sO1[(g+8)*132 + c+1] = leaky(acc2[jj][3] + sB4[c+1]);
    }
    __syncthreads();

    if (t < 16){   // LN2 stats
        float sum = 0.f, ss = 0.f;
        #pragma unroll 8
        for (int j = 0; j < 128; j++){ float v = sO1[t*132 + j]; sum += v; ss += v*v; }
        float mu = sum * (1.f/128.f);
        float var = ss * (1.f/128.f) - mu*mu;
        sMu[t] = mu; sIs[t] = rsqrtf(var + EPS);
    }
    __syncthreads();
    #pragma unroll
    for (int e = 0; e < 8; e++){
        int idx = t + 256*e;
        int r = idx >> 7, c = idx & 127;
        out[(g0 + r)*128 + c] = (sO1[r*132 + c] - sMu[r]) * sIs[r] * sG4[c] + sBe4[c];
    }
}

// ---------------- host ----------------
extern "C" void kernel_launch(void* const* d_in, const int* in_sizes, int n_in,
                              void* d_out, int out_size)
{
    const float* feat = (const float*)d_in[0];
    const int*   batch = (const int*)d_in[1];
    const float* W1 = (const float*)d_in[2];
    const float* b1 = (const float*)d_in[3];
    const float* g1 = (const float*)d_in[4];
    const float* be1= (const float*)d_in[5];
    const float* W2 = (const float*)d_in[6];
    const float* b2 = (const float*)d_in[7];
    const float* W3 = (const float*)d_in[8];
    const float* b3 = (const float*)d_in[9];
    const float* g3 = (const float*)d_in[10];
    const float* be3= (const float*)d_in[11];
    const float* W4 = (const float*)d_in[12];
    const float* b4 = (const float*)d_in[13];
    const float* g4 = (const float*)d_in[14];
    const float* be4= (const float*)d_in[15];

    int nrows = in_sizes[0] / 128;

    const int att_smem = ATT_SMEM_WORDS * 4;   // 71,968 B -> 3 CTAs/SM
    const int fin_smem = FIN_SMEM_WORDS * 4;   // 89,984 B -> 2 CTAs/SM
    cudaFuncSetAttribute(att_kernel,   cudaFuncAttributeMaxDynamicSharedMemorySize, att_smem);
    cudaFuncSetAttribute(final_kernel, cudaFuncAttributeMaxDynamicSharedMemorySize, fin_smem);

    detect_kernel<<<1, 256>>>(batch, nrows);
    bounds_kernel<<<NGRAPH / 256, 256>>>(batch, nrows);
    prep_kernel<<<304, 256>>>(W1, W3, W4);
    att_kernel<<<nrows / 64, 256, att_smem>>>(feat, b1, g1, be1, W2, b2);
    aggregate_kernel<<<NGRAPH, 256>>>(feat);
    final_kernel<<<NGRAPH / 16, 256, fin_smem>>>(b3, g3, be3, b4, g4, be4, (float*)d_out);
}

// round 17
// speedup vs baseline: 1.0763x; 1.0763x over previous
#include <cuda_runtime.h>
#include <cuda_bf16.h>
#include <cstdint>

#define NGRAPH 4096
#define EPS 1e-6f

// ---------------- device scratch ----------------
__device__ __align__(16) float g_att[262144 * 8];          // exp attention, unnormalized [N,8]
__device__ __align__(16) float g_outflat[NGRAPH * 1024];   // aggregated [B, H*D]
__device__ __align__(16) unsigned int g_W1h[64 * 64];      // W1 packed bf16x2 [n][kw]
__device__ __align__(16) unsigned int g_W1l[64 * 64];
__device__ __align__(16) unsigned int g_W3h[128 * 512];    // W3 packed [n][kw]
__device__ __align__(16) unsigned int g_W3l[128 * 512];
__device__ __align__(16) unsigned int g_W4h[128 * 64];     // W4 packed [n][kw]
__device__ __align__(16) unsigned int g_W4l[128 * 64];
__device__ int g_seglo[NGRAPH + 1];
__device__ int g_is64;

__device__ __forceinline__ float leaky(float x){ return x > 0.f ? x : 0.01f * x; }

// split (x,y) into bf16 hi/lo pairs packed as bf16x2 words (x in LOW half).
// Fast path: packed cvt.rn.bf16x2.f32 (1 instr per pair) + shift/mask residual
// recovery. Bitwise-identical to the scalar __float2bfloat16_rn version.
__device__ __forceinline__ void split2(float x, float y, uint32_t& h, uint32_t& l){
    uint32_t hh;
    asm("cvt.rn.bf16x2.f32 %0, %1, %2;" : "=r"(hh) : "f"(y), "f"(x));  // y->high, x->low
    float hx = __uint_as_float(hh << 16);
    float hy = __uint_as_float(hh & 0xffff0000u);
    float rx = x - hx;
    float ry = y - hy;
    uint32_t ll;
    asm("cvt.rn.bf16x2.f32 %0, %1, %2;" : "=r"(ll) : "f"(ry), "f"(rx));
    h = hh; l = ll;
}

// D += A(16x16 bf16) * B(16x8 bf16), fp32 accumulate
__device__ __forceinline__ void mma_bf16(float* c,
    uint32_t a0, uint32_t a1, uint32_t a2, uint32_t a3, uint32_t b0, uint32_t b1){
    asm volatile(
      "mma.sync.aligned.m16n8k16.row.col.f32.bf16.bf16.f32 "
      "{%0,%1,%2,%3}, {%4,%5,%6,%7}, {%8,%9}, {%0,%1,%2,%3};\n"
      : "+f"(c[0]), "+f"(c[1]), "+f"(c[2]), "+f"(c[3])
      : "r"(a0), "r"(a1), "r"(a2), "r"(a3), "r"(b0), "r"(b1));
}

// ldmatrix x4 (non-transposed, b16)
__device__ __forceinline__ void ldsm_x4(uint32_t& r0, uint32_t& r1, uint32_t& r2, uint32_t& r3,
                                        uint32_t addr){
    asm volatile("ldmatrix.sync.aligned.m8n8.x4.shared.b16 {%0,%1,%2,%3}, [%4];"
        : "=r"(r0), "=r"(r1), "=r"(r2), "=r"(r3) : "r"(addr));
}

// Parallel batch dtype detection (int32 loads only).
__global__ void detect_kernel(const int* __restrict__ batch, int n){
    __shared__ int bad;
    if (threadIdx.x == 0) bad = 0;
    __syncthreads();
    int base = n / 2;
    int i = threadIdx.x;
    int lo = batch[base + 2*i];
    int hi = batch[base + 2*i + 1];
    if (hi != 0 || lo < 0 || lo >= NGRAPH) bad = 1;
    __syncthreads();
    if (threadIdx.x == 0) g_is64 = (bad == 0);
}

__device__ __forceinline__ int bat(const int* b, int i, int is64){
    return is64 ? b[2*i] : b[i];
}

__device__ __forceinline__ int lbound(const int* b, int n, int val, int is64){
    int lo = 0, hi = n;
    while (lo < hi){
        int mid = (lo + hi) >> 1;
        if (bat(b, mid, is64) < val) lo = mid + 1; else hi = mid;
    }
    return lo;
}

// ---------------- segment bounds: one thread per graph ----------------
__global__ void bounds_kernel(const int* __restrict__ batch, int n){
    int g = blockIdx.x * 256 + threadIdx.x;
    int is64 = g_is64;
    if (g < NGRAPH) g_seglo[g] = lbound(batch, n, g, is64);
    if (g == 0)     g_seglo[NGRAPH] = n;
}

// ---------------- weight prep: pack W1/W3/W4 as bf16x2 hi/lo, [n][kword] ----------------
// Index mapping chosen so GLOBAL READS are coalesced (n fast-varying).
__global__ void prep_kernel(const float* __restrict__ W1,
                            const float* __restrict__ W3,
                            const float* __restrict__ W4){
    int idx = blockIdx.x * 256 + threadIdx.x;
    if (idx < 4096){                               // W1: [128 k][64 n] -> [64 n][64 kw]
        int n = idx & 63, kw = idx >> 6;
        uint32_t h, l;
        split2(W1[(2*kw)*64 + n], W1[(2*kw+1)*64 + n], h, l);
        g_W1h[n*64 + kw] = h; g_W1l[n*64 + kw] = l;
        return;
    }
    int j = idx - 4096;
    if (j < 65536){                                // W3: [1024 k][128 n] -> [128 n][512 kw]
        int n = j & 127, kw = j >> 7;
        uint32_t h, l;
        split2(W3[(2*kw)*128 + n], W3[(2*kw+1)*128 + n], h, l);
        g_W3h[n*512 + kw] = h; g_W3l[n*512 + kw] = l;
        return;
    }
    int m = j - 65536;
    if (m < 8192){                                 // W4: [128 k][128 n] -> [128 n][64 kw]
        int n = m & 127, kw = m >> 7;
        uint32_t h, l;
        split2(W4[(2*kw)*128 + n], W4[(2*kw+1)*128 + n], h, l);
        g_W4h[n*64 + kw] = h; g_W4l[n*64 + kw] = l;
    }
}

// ---------------- Pass A: GEMM1 (bf16 3-term, ldmatrix, 4m x 2n warps) + leaky + LN + GEMM2 + exp ----
// 128 rows / block, 256 threads, 2048 blocks (R15-proven shape).
#define ATT_SMEM_WORDS (8704 + 8704 + 4352 + 4352 + 512 + 64*3 + 8 + 256)

__global__ __launch_bounds__(256) void att_kernel(
    const float* __restrict__ feat,
    const float* __restrict__ b1,
    const float* __restrict__ g1, const float* __restrict__ be1,
    const float* __restrict__ W2, const float* __restrict__ b2)
{
    extern __shared__ uint32_t smw[];
    uint32_t* sAh = smw;                 // 128 x 68 = 8704
    uint32_t* sAl = sAh + 8704;          // 8704
    uint32_t* sWh = sAl + 8704;          // 64 x 68 = 4352
    uint32_t* sWl = sWh + 4352;          // 4352
    float* sW2  = (float*)(sWl + 4352);  // 512
    float* sB1  = sW2 + 512;             // 64
    float* sG1  = sB1 + 64;              // 64
    float* sBe1 = sG1 + 64;              // 64
    float* sB2  = sBe1 + 64;             // 8
    float* sMu  = sB2 + 8;               // 128
    float* sIs  = sMu + 128;             // 128
    float* sH   = (float*)sAh;           // alias, stride 65 (8320 <= 8704)

    int t = threadIdx.x;
    int row0 = blockIdx.x * 128;
    int wid = t >> 5, lane = t & 31;
    int g = lane >> 2, t4 = lane & 3;
    int mw = wid & 3, nw = wid >> 2;

    {   // stage A: feat 128x128 -> bf16 hi/lo packed (4096 float4, 16/thread)
        const float4* gsrc = (const float4*)(feat + (size_t)row0 * 128);
        #pragma unroll
        for (int e = 0; e < 16; e++){
            int i4 = t + 256*e;
            int r = i4 >> 5, c4 = i4 & 31;
            float4 a = gsrc[i4];
            uint2 h, l;
            split2(a.x, a.y, h.x, l.x);
            split2(a.z, a.w, h.y, l.y);
            int base = r*68 + 2*c4;
            *(uint2*)&sAh[base] = h;
            *(uint2*)&sAl[base] = l;
        }
    }
    {   // stage B: copy prepacked W1 hi/lo
        #pragma unroll
        for (int e = 0; e < 4; e++){
            int i4 = t + 256*e;
            int n = i4 >> 4, c4 = i4 & 15;
            *(uint4*)&sWh[n*68 + 4*c4] = *(const uint4*)&g_W1h[n*64 + 4*c4];
            *(uint4*)&sWl[n*68 + 4*c4] = *(const uint4*)&g_W1l[n*64 + 4*c4];
        }
    }
    if (t < 128) ((float4*)sW2)[t] = ((const float4*)W2)[t];
    if (t < 64){ sB1[t] = b1[t]; sG1[t] = g1[t]; sBe1[t] = be1[t]; }
    if (t < 8)  sB2[t] = b2[t];
    __syncthreads();

    // GEMM1: warp = rows [mw*32,+32) x cols [nw*32,+32). K=128 -> 8 k16-steps.
    float acc[2][4][4];
    #pragma unroll
    for (int mt = 0; mt < 2; mt++)
        #pragma unroll
        for (int jn = 0; jn < 4; jn++){
            acc[mt][jn][0]=0.f; acc[mt][jn][1]=0.f; acc[mt][jn][2]=0.f; acc[mt][jn][3]=0.f;
        }

    uint32_t aBaseH[2], aBaseL[2];
    #pragma unroll
    for (int mt = 0; mt < 2; mt++){
        int rowf = mw*32 + mt*16 + (lane & 7) + ((lane >> 3) & 1) * 8;
        int kws  = ((lane >> 4) & 1) * 4;
        aBaseH[mt] = (uint32_t)__cvta_generic_to_shared(sAh + rowf*68 + kws);
        aBaseL[mt] = (uint32_t)__cvta_generic_to_shared(sAl + rowf*68 + kws);
    }
    uint32_t bBaseH[2], bBaseL[2];
    #pragma unroll
    for (int jp = 0; jp < 2; jp++){
        int nf  = nw*32 + (2*jp + ((lane >> 4) & 1)) * 8 + (lane & 7);
        int kws = ((lane >> 3) & 1) * 4;
        bBaseH[jp] = (uint32_t)__cvta_generic_to_shared(sWh + nf*68 + kws);
        bBaseL[jp] = (uint32_t)__cvta_generic_to_shared(sWl + nf*68 + kws);
    }

    #pragma unroll 2
    for (int ks = 0; ks < 8; ks++){
        uint32_t off = (uint32_t)ks * 32;   // 8 words per k16-step
        uint32_t ah[2][4], al[2][4];
        #pragma unroll
        for (int mt = 0; mt < 2; mt++){
            ldsm_x4(ah[mt][0],ah[mt][1],ah[mt][2],ah[mt][3], aBaseH[mt] + off);
            ldsm_x4(al[mt][0],al[mt][1],al[mt][2],al[mt][3], aBaseL[mt] + off);
        }
        #pragma unroll
        for (int jp = 0; jp < 2; jp++){
            uint32_t bh0,bh1,bh2,bh3, bl0,bl1,bl2,bl3;
            ldsm_x4(bh0,bh1,bh2,bh3, bBaseH[jp] + off);
            ldsm_x4(bl0,bl1,bl2,bl3, bBaseL[jp] + off);
            #pragma unroll
            for (int mt = 0; mt < 2; mt++){
                mma_bf16(acc[mt][2*jp],   ah[mt][0],ah[mt][1],ah[mt][2],ah[mt][3], bh0,bh1);
                mma_bf16(acc[mt][2*jp],   al[mt][0],al[mt][1],al[mt][2],al[mt][3], bh0,bh1);
                mma_bf16(acc[mt][2*jp],   ah[mt][0],ah[mt][1],ah[mt][2],ah[mt][3], bl0,bl1);
                mma_bf16(acc[mt][2*jp+1], ah[mt][0],ah[mt][1],ah[mt][2],ah[mt][3], bh2,bh3);
                mma_bf16(acc[mt][2*jp+1], al[mt][0],al[mt][1],al[mt][2],al[mt][3], bh2,bh3);
                mma_bf16(acc[mt][2*jp+1], ah[mt][0],ah[mt][1],ah[mt][2],ah[mt][3], bl2,bl3);
            }
        }
    }
    __syncthreads();   // all sAh/sAl reads done before aliasing sAh as sH

    {   // epilogue: bias + leaky -> sH (stride 65)
        #pragma unroll
        for (int mt = 0; mt < 2; mt++){
            int rA = mw*32 + mt*16 + g, rB = rA + 8;
            #pragma unroll
            for (int jn = 0; jn < 4; jn++){
                int c = nw*32 + jn*8 + 2*t4;
                sH[rA*65 + c]     = leaky(acc[mt][jn][0] + sB1[c]);
                sH[rA*65 + c + 1] = leaky(acc[mt][jn][1] + sB1[c+1]);
                sH[rB*65 + c]     = leaky(acc[mt][jn][2] + sB1[c]);
                sH[rB*65 + c + 1] = leaky(acc[mt][jn][3] + sB1[c+1]);
            }
        }
    }
    __syncthreads();

    if (t < 128){   // LN stats per row
        float sum = 0.f, ss = 0.f;
        #pragma unroll 8
        for (int j = 0; j < 64; j++){ float v = sH[t*65 + j]; sum += v; ss += v*v; }
        float mu = sum * (1.f/64.f);
        float var = ss * (1.f/64.f) - mu*mu;
        sMu[t] = mu; sIs[t] = rsqrtf(var + EPS);
    }
    __syncthreads();

    {   // GEMM2 (64->8) + exp (fp32, exact)
        int row = t >> 1, half = t & 1, kb = half * 4;
        float mu = sMu[row], is = sIs[row];
        float a0=0.f, a1=0.f, a2=0.f, a3=0.f;
        #pragma unroll 4
        for (int j = 0; j < 64; j++){
            float hn = (sH[row*65 + j] - mu) * is * sG1[j] + sBe1[j];
            a0 += hn * sW2[j*8 + kb + 0];
            a1 += hn * sW2[j*8 + kb + 1];
            a2 += hn * sW2[j*8 + kb + 2];
            a3 += hn * sW2[j*8 + kb + 3];
        }
        int grow = row0 + row;
        float4 o;
        o.x = __expf(a0 + sB2[kb+0]);
        o.y = __expf(a1 + sB2[kb+1]);
        o.z = __expf(a2 + sB2[kb+2]);
        o.w = __expf(a3 + sB2[kb+3]);
        *(float4*)&g_att[grow*8 + kb] = o;
    }
}

// ---------------- Pass B: segment softmax + aggregation, 2 heads/thread ----------------
__global__ __launch_bounds__(256) void aggregate_kernel(const float* __restrict__ feat){
    int gi = blockIdx.x;
    __shared__ __align__(16) float sF[32][128];
    __shared__ __align__(16) float sAtt[32][8];
    __shared__ __align__(16) float sRed[128][8];    // rg=1 partial acc
    __shared__ float sS[128][2];                    // rg=1 partial head sums

    int t = threadIdx.x;
    int lo = g_seglo[gi], hi = g_seglo[gi + 1];
    int rg = t >> 7;              // 0 or 1
    int slot = t & 127;
    int hp = slot >> 5;           // head pair 0..3 -> heads 2hp, 2hp+1
    int cq = slot & 31;           // col quad

    float4 acc0 = make_float4(0.f,0.f,0.f,0.f);
    float4 acc1 = make_float4(0.f,0.f,0.f,0.f);
    float ss0 = 0.f, ss1 = 0.f;

    for (int base = lo; base < hi; base += 32){
        int cnt = min(32, hi - base);
        __syncthreads();
        for (int idx4 = t; idx4 < cnt*32; idx4 += 256){
            int r = idx4 >> 5, c4 = idx4 & 31;
            *(float4*)&sF[r][4*c4] = *(const float4*)&feat[(size_t)(base + r) * 128 + 4*c4];
        }
        if (t < cnt*8){
            int r = t >> 3, k = t & 7;
            sAtt[r][k] = g_att[(base + r)*8 + k];
        }
        __syncthreads();
        int rlo = rg * 16, rhi = min(cnt, rlo + 16);
        for (int r = rlo; r < rhi; r++){
            float a0 = sAtt[r][2*hp];
            float a1 = sAtt[r][2*hp + 1];
            ss0 += a0; ss1 += a1;
            float4 f = *(const float4*)&sF[r][cq*4];
            acc0.x += a0*f.x; acc0.y += a0*f.y; acc0.z += a0*f.z; acc0.w += a0*f.w;
            acc1.x += a1*f.x; acc1.y += a1*f.y; acc1.z += a1*f.z; acc1.w += a1*f.w;
        }
    }
    __syncthreads();
    if (rg == 1){
        *(float4*)&sRed[slot][0] = acc0;
        *(float4*)&sRed[slot][4] = acc1;
        sS[slot][0] = ss0; sS[slot][1] = ss1;
    }
    __syncthreads();
    if (rg == 0){
        float4 p0 = *(const float4*)&sRed[slot][0];
        float4 p1 = *(const float4*)&sRed[slot][4];
        acc0.x += p0.x; acc0.y += p0.y; acc0.z += p0.z; acc0.w += p0.w;
        acc1.x += p1.x; acc1.y += p1.y; acc1.z += p1.z; acc1.w += p1.w;
        float tot0 = ss0 + sS[slot][0];
        float tot1 = ss1 + sS[slot][1];
        float inv0 = (hi > lo) ? 1.f / tot0 : 0.f;
        float inv1 = (hi > lo) ? 1.f / tot1 : 0.f;
        acc0.x *= inv0; acc0.y *= inv0; acc0.z *= inv0; acc0.w *= inv0;
        acc1.x *= inv1; acc1.y *= inv1; acc1.z *= inv1; acc1.w *= inv1;
        *(float4*)&g_outflat[(size_t)gi*1024 + (2*hp)*128 + cq*4]     = acc0;
        *(float4*)&g_outflat[(size_t)gi*1024 + (2*hp + 1)*128 + cq*4] = acc1;
    }
}

// ---------------- Pass C: GEMM3(bf16 3-term)+leaky+LN, GEMM4(bf16 3-term)+leaky+LN ----------------
// 16 graphs / block, 256 blocks, 256 threads. Warp w owns n-cols [w*16, +16).
#define FIN_SMEM_WORDS (8704 + 8704 + 1088 + 1088 + 2112 + 128*6 + 32)

__global__ __launch_bounds__(256) void final_kernel(
    const float* __restrict__ b3,
    const float* __restrict__ g3, const float* __restrict__ be3,
    const float* __restrict__ b4,
    const float* __restrict__ g4, const float* __restrict__ be4,
    float* __restrict__ out)
{
    extern __shared__ uint32_t smw[];
    uint32_t* sWh = smw;                 // 128 x 68 = 8704
    uint32_t* sWl = sWh + 8704;          // 8704
    uint32_t* sAh = sWl + 8704;          // 16 x 68 = 1088
    uint32_t* sAl = sAh + 1088;          // 1088
    float* sO1 = (float*)(sAl + 1088);   // 16 x 132 = 2112 (fp32 scratch)
    float* sB3 = sO1 + 2112;
    float* sG3 = sB3 + 128;
    float* sBe3= sG3 + 128;
    float* sB4 = sBe3+ 128;
    float* sG4 = sB4 + 128;
    float* sBe4= sG4 + 128;
    float* sMu = sBe4+ 128;              // 16
    float* sIs = sMu + 16;               // 16

    int t = threadIdx.x;
    int g0 = blockIdx.x * 16;
    int wid = t >> 5, lane = t & 31;
    int g = lane >> 2, t4 = lane & 3;

    if (t < 128){
        sB3[t]=b3[t]; sG3[t]=g3[t]; sBe3[t]=be3[t];
        sB4[t]=b4[t]; sG4[t]=g4[t]; sBe4[t]=be4[t];
    }

    uint32_t aBaseH, aBaseL, bBaseH, bBaseL;
    {
        int rowf = (lane & 7) + ((lane >> 3) & 1) * 8;
        int kwsA = ((lane >> 4) & 1) * 4;
        aBaseH = (uint32_t)__cvta_generic_to_shared(sAh + rowf*68 + kwsA);
        aBaseL = (uint32_t)__cvta_generic_to_shared(sAl + rowf*68 + kwsA);
        int nf   = wid*16 + ((lane >> 4) & 1) * 8 + (lane & 7);
        int kwsB = ((lane >> 3) & 1) * 4;
        bBaseH = (uint32_t)__cvta_generic_to_shared(sWh + nf*68 + kwsB);
        bBaseL = (uint32_t)__cvta_generic_to_shared(sWl + nf*68 + kwsB);
    }

    // ---- GEMM3: [16,1024] @ [1024,128], 8 k-tiles of 128 (8 k16-steps each) ----
    float acc[2][4];
    acc[0][0]=acc[0][1]=acc[0][2]=acc[0][3]=0.f;
    acc[1][0]=acc[1][1]=acc[1][2]=acc[1][3]=0.f;

    for (int kt = 0; kt < 8; kt++){
        __syncthreads();
        {   // stage A slice 16x128 -> bf16 hi/lo (512 float4, 2/thread)
            #pragma unroll
            for (int e = 0; e < 2; e++){
                int i4 = t + 256*e;
                int r = i4 >> 5, c4 = i4 & 31;
                float4 a = *(const float4*)&g_outflat[(size_t)(g0 + r)*1024 + kt*128 + 4*c4];
                uint2 h, l;
                split2(a.x, a.y, h.x, l.x);
                split2(a.z, a.w, h.y, l.y);
                int base = r*68 + 2*c4;
                *(uint2*)&sAh[base] = h;
                *(uint2*)&sAl[base] = l;
            }
        }
        {   // stage W3 hi/lo k-tile
            #pragma unroll
            for (int e = 0; e < 8; e++){
                int i4 = t + 256*e;
                int n = i4 >> 4, c4 = i4 & 15;
                *(uint4*)&sWh[n*68 + 4*c4] = *(const uint4*)&g_W3h[n*512 + kt*64 + 4*c4];
                *(uint4*)&sWl[n*68 + 4*c4] = *(const uint4*)&g_W3l[n*512 + kt*64 + 4*c4];
            }
        }
        __syncthreads();

        #pragma unroll 2
        for (int ks = 0; ks < 8; ks++){
            uint32_t off = (uint32_t)ks * 32;
            uint32_t ah0,ah1,ah2,ah3, al0,al1,al2,al3;
            ldsm_x4(ah0,ah1,ah2,ah3, aBaseH + off);
            ldsm_x4(al0,al1,al2,al3, aBaseL + off);
            uint32_t bh0,bh1,bh2,bh3, bl0,bl1,bl2,bl3;
            ldsm_x4(bh0,bh1,bh2,bh3, bBaseH + off);
            ldsm_x4(bl0,bl1,bl2,bl3, bBaseL + off);
            mma_bf16(acc[0], ah0,ah1,ah2,ah3, bh0,bh1);
            mma_bf16(acc[0], al0,al1,al2,al3, bh0,bh1);
            mma_bf16(acc[0], ah0,ah1,ah2,ah3, bl0,bl1);
            mma_bf16(acc[1], ah0,ah1,ah2,ah3, bh2,bh3);
            mma_bf16(acc[1], al0,al1,al2,al3, bh2,bh3);
            mma_bf16(acc[1], ah0,ah1,ah2,ah3, bl2,bl3);
        }
    }
    __syncthreads();

    {   // epilogue GEMM3 -> sO1 (fp32); stage W4 hi/lo into sWh/sWl
        #pragma unroll
        for (int jj = 0; jj < 2; jj++){
            int c = wid*16 + jj*8 + 2*t4;
            sO1[g*132 + c]       = leaky(acc[jj][0] + sB3[c]);
            sO1[g*132 + c + 1]   = leaky(acc[jj][1] + sB3[c+1]);
            sO1[(g+8)*132 + c]   = leaky(acc[jj][2] + sB3[c]);
            sO1[(g+8)*132 + c+1] = leaky(acc[jj][3] + sB3[c+1]);
        }
        #pragma unroll
        for (int e = 0; e < 8; e++){
            int i4 = t + 256*e;
            int n = i4 >> 4, c4 = i4 & 15;
            *(uint4*)&sWh[n*68 + 4*c4] = *(const uint4*)&g_W4h[n*64 + 4*c4];
            *(uint4*)&sWl[n*68 + 4*c4] = *(const uint4*)&g_W4l[n*64 + 4*c4];
        }
    }
    __syncthreads();

    if (t < 16){   // LN1 stats
        float sum = 0.f, ss = 0.f;
        #pragma unroll 8
        for (int j = 0; j < 128; j++){ float v = sO1[t*132 + j]; sum += v; ss += v*v; }
        float mu = sum * (1.f/128.f);
        float var = ss * (1.f/128.f) - mu*mu;
        sMu[t] = mu; sIs[t] = rsqrtf(var + EPS);
    }
    __syncthreads();
    {   // LN1 apply + bf16 split into sAh/sAl (1024 words, 4/thread)
        #pragma unroll
        for (int e = 0; e < 4; e++){
            int w = t + 256*e;
            int r = w >> 6, kw = w & 63;
            int c = 2*kw;
            float mu = sMu[r], is = sIs[r];
            float v0 = (sO1[r*132 + c]     - mu) * is * sG3[c]   + sBe3[c];
            float v1 = (sO1[r*132 + c + 1] - mu) * is * sG3[c+1] + sBe3[c+1];
            uint32_t h, l;
            split2(v0, v1, h, l);
            sAh[r*68 + kw] = h;
            sAl[r*68 + kw] = l;
        }
    }
    __syncthreads();

    // ---- GEMM4: [16,128] @ [128,128] (8 k16-steps) ----
    float acc2[2][4];
    acc2[0][0]=acc2[0][1]=acc2[0][2]=acc2[0][3]=0.f;
    acc2[1][0]=acc2[1][1]=acc2[1][2]=acc2[1][3]=0.f;

    #pragma unroll 2
    for (int ks = 0; ks < 8; ks++){
        uint32_t off = (uint32_t)ks * 32;
        uint32_t ah0,ah1,ah2,ah3, al0,al1,al2,al3;
        ldsm_x4(ah0,ah1,ah2,ah3, aBaseH + off);
        ldsm_x4(al0,al1,al2,al3, aBaseL + off);
        uint32_t bh0,bh1,bh2,bh3, bl0,bl1,bl2,bl3;
        ldsm_x4(bh0,bh1,bh2,bh3, bBaseH + off);
        ldsm_x4(bl0,bl1,bl2,bl3, bBaseL + off);
        mma_bf16(acc2[0], ah0,ah1,ah2,ah3, bh0,bh1);
        mma_bf16(acc2[0], al0,al1,al2,al3, bh0,bh1);
        mma_bf16(acc2[0], ah0,ah1,ah2,ah3, bl0,bl1);
        mma_bf16(acc2[1], ah0,ah1,ah2,ah3, bh2,bh3);
        mma_bf16(acc2[1], al0,al1,al2,al3, bh2,bh3);
        mma_bf16(acc2[1], ah0,ah1,ah2,ah3, bl2,bl3);
    }
    __syncthreads();

    // epilogue GEMM4 -> sO1 (reuse as sO2)
    #pragma unroll
    for (int jj = 0; jj < 2; jj++){
        int c = wid*16 + jj*8 + 2*t4;
        sO1[g*132 + c]       = leaky(acc2[jj][0] + sB4[c]);
        sO1[g*132 + c + 1]   = leaky(acc2[jj][1] + sB4[c+1]);
        sO1[(g+8)*132 + c]   = leaky(acc2[jj][2] + sB4[c]);
        sO1[(g+8)*132 + c+1] = leaky(acc2[jj][3] + sB4[c+1]);
    }
    __syncthreads();

    if (t < 16){   // LN2 stats
        float sum = 0.f, ss = 0.f;
        #pragma unroll 8
        for (int j = 0; j < 128; j++){ float v = sO1[t*132 + j]; sum += v; ss += v*v; }
        float mu = sum * (1.f/128.f);
        float var = ss * (1.f/128.f) - mu*mu;
        sMu[t] = mu; sIs[t] = rsqrtf(var + EPS);
    }
    __syncthreads();
    #pragma unroll
    for (int e = 0; e < 8; e++){
        int idx = t + 256*e;
        int r = idx >> 7, c = idx & 127;
        out[(g0 + r)*128 + c] = (sO1[r*132 + c] - sMu[r]) * sIs[r] * sG4[c] + sBe4[c];
    }
}

// ---------------- host ----------------
extern "C" void kernel_launch(void* const* d_in, const int* in_sizes, int n_in,
                              void* d_out, int out_size)
{
    const float* feat = (const float*)d_in[0];
    const int*   batch = (const int*)d_in[1];
    const float* W1 = (const float*)d_in[2];
    const float* b1 = (const float*)d_in[3];
    const float* g1 = (const float*)d_in[4];
    const float* be1= (const float*)d_in[5];
    const float* W2 = (const float*)d_in[6];
    const float* b2 = (const float*)d_in[7];
    const float* W3 = (const float*)d_in[8];
    const float* b3 = (const float*)d_in[9];
    const float* g3 = (const float*)d_in[10];
    const float* be3= (const float*)d_in[11];
    const float* W4 = (const float*)d_in[12];
    const float* b4 = (const float*)d_in[13];
    const float* g4 = (const float*)d_in[14];
    const float* be4= (const float*)d_in[15];

    int nrows = in_sizes[0] / 128;

    const int att_smem = ATT_SMEM_WORDS * 4;   // 108,320 B -> 2 CTAs/SM
    const int fin_smem = FIN_SMEM_WORDS * 4;   //  89,984 B -> 2 CTAs/SM
    cudaFuncSetAttribute(att_kernel,   cudaFuncAttributeMaxDynamicSharedMemorySize, att_smem);
    cudaFuncSetAttribute(final_kernel, cudaFuncAttributeMaxDynamicSharedMemorySize, fin_smem);

    detect_kernel<<<1, 256>>>(batch, nrows);
    bounds_kernel<<<NGRAPH / 256, 256>>>(batch, nrows);
    prep_kernel<<<304, 256>>>(W1, W3, W4);
    att_kernel<<<nrows / 128, 256, att_smem>>>(feat, b1, g1, be1, W2, b2);
    aggregate_kernel<<<NGRAPH, 256>>>(feat);
    final_kernel<<<NGRAPH / 16, 256, fin_smem>>>(b3, g3, be3, b4, g4, be4, (float*)d_out);
}